// round 1
// baseline (speedup 1.0000x reference)
#include <cuda_runtime.h>
#include <math.h>

#define TT  100
#define HH  50
#define ZZ  10
#define OUTD 65          // ZZ + ZZ*(ZZ+1)/2
#define NTRI 55          // ZZ*(ZZ+1)/2
#define LN_EPS 1e-6f

// scratch for hs (T x H) — __device__ global, no allocation
__device__ float g_hs[TT * HH];

// ---------------------------------------------------------------------------
// Kernel 1: sequential GRU recurrence with layernormed gates.
// Single CTA, 192 threads: gate g = tid/64, column j = tid%64 (active j<50).
// ---------------------------------------------------------------------------
__global__ void __launch_bounds__(192, 1) gru_recurrence_kernel(
    const float* __restrict__ carry_init,
    const float* __restrict__ W_hr, const float* __restrict__ b_hr,
    const float* __restrict__ s_r,  const float* __restrict__ o_r,
    const float* __restrict__ W_hz, const float* __restrict__ b_hz,
    const float* __restrict__ s_z,  const float* __restrict__ o_z,
    const float* __restrict__ W_hn, const float* __restrict__ b_hn,
    const float* __restrict__ s_n,  const float* __restrict__ o_n)
{
    __shared__ float Wsh[3][HH][HH];     // [gate][i][j]  (30 KB)
    __shared__ float bsh[3][HH], ssh[3][HH], osh_[3][HH];
    __shared__ float h_sh[HH];
    __shared__ float gate_sh[3][HH];
    __shared__ float part_s[6], part_q[6];

    const int tid  = threadIdx.x;
    const int g    = tid >> 6;           // 0..2
    const int j    = tid & 63;           // 0..63, active < 50
    const int lane = tid & 31;
    const int warp = tid >> 5;           // 0..5  (gate g owns warps 2g, 2g+1)

    // stage weights / params into shared
    const float* Wg[3] = {W_hr, W_hz, W_hn};
    const float* bg[3] = {b_hr, b_hz, b_hn};
    const float* sg[3] = {s_r,  s_z,  s_n };
    const float* og[3] = {o_r,  o_z,  o_n };
    for (int gg = 0; gg < 3; gg++) {
        float*       wdst = &Wsh[gg][0][0];
        const float* wsrc = Wg[gg];
        for (int k = tid; k < HH * HH; k += 192) wdst[k] = wsrc[k];
        if (tid < HH) {
            bsh [gg][tid] = bg[gg][tid];
            ssh [gg][tid] = sg[gg][tid];
            osh_[gg][tid] = og[gg][tid];
        }
    }
    if (tid < HH) h_sh[tid] = carry_init[tid];
    __syncthreads();

    for (int t = 0; t < TT; t++) {
        // ---- pre-activation matvec: acc = b[g][j] + sum_i h[i]*W[g][i][j]
        float acc = 0.f;
        if (j < HH) {
            acc = bsh[g][j];
            #pragma unroll
            for (int i = 0; i < HH; i++)
                acc = fmaf(h_sh[i], Wsh[g][i][j], acc);
        }
        // ---- layernorm stats (sum, sumsq) over the 50 columns of this gate
        float v = (j < HH) ? acc : 0.f;
        float s = v, q = v * v;
        #pragma unroll
        for (int off = 16; off; off >>= 1) {
            s += __shfl_xor_sync(0xffffffffu, s, off);
            q += __shfl_xor_sync(0xffffffffu, q, off);
        }
        if (lane == 0) { part_s[warp] = s; part_q[warp] = q; }
        __syncthreads();                                    // S1

        float S    = part_s[2 * g] + part_s[2 * g + 1];
        float Q    = part_q[2 * g] + part_q[2 * g + 1];
        float mean = S * (1.0f / HH);
        float var  = Q * (1.0f / HH) - mean * mean;
        float inv  = rsqrtf(var + LN_EPS);

        if (j < HH) {
            float nrm = (acc - mean) * inv * ssh[g][j] + osh_[g][j];
            float outv;
            if (g < 2) outv = 1.0f / (1.0f + expf(-nrm));   // sigmoid (r, z)
            else       outv = nrm;                          // pre-tanh ln for n
            gate_sh[g][j] = outv;
        }
        __syncthreads();                                    // S2

        if (tid < HH) {
            float r  = gate_sh[0][tid];
            float z  = gate_sh[1][tid];
            float ln = gate_sh[2][tid];
            float n  = tanhf(r * ln);
            float hn = (1.0f - z) * n + z * h_sh[tid];
            h_sh[tid]         = hn;
            g_hs[t * HH + tid] = hn;
        }
        __syncthreads();                                    // S3
    }
}

// ---------------------------------------------------------------------------
// Kernel 2: per-timestep dense + natural-parameter epilogue.
// grid = T blocks (one per timestep), 128 threads each.
// Output layout (fp32): [Sigma T*Z*Z][mu T*Z][J T*Z*Z][h_nat T*Z]
// ---------------------------------------------------------------------------
__global__ void __launch_bounds__(128, 1) nat_kernel(
    const float* __restrict__ W_dense,
    const float* __restrict__ b_dense,
    float* __restrict__ out)
{
    const int t   = blockIdx.x;
    const int tid = threadIdx.x;

    __shared__ float hsh[HH];
    __shared__ float osh[OUTD];
    __shared__ float L [ZZ][ZZ];
    __shared__ float Li[ZZ][ZZ];
    __shared__ float Jsh[ZZ][ZZ];

    if (tid < HH) hsh[tid] = g_hs[t * HH + tid];
    __syncthreads();

    // dense: out[o] = b[o] + sum_i hs[t][i] * W_dense[i][o]
    if (tid < OUTD) {
        float a = b_dense[tid];
        #pragma unroll
        for (int i = 0; i < HH; i++)
            a = fmaf(hsh[i], W_dense[i * OUTD + tid], a);
        osh[tid] = a;
    }
    __syncthreads();

    // build lower-triangular L from flat part; softplus on diagonal
    if (tid < NTRI) {
        int k = tid;
        int r = 0;
        while (k >= (r + 1) * (r + 2) / 2) r++;       // row of tril index k
        int c = k - r * (r + 1) / 2;
        float v = osh[ZZ + k];
        if (c == r) {
            // stable softplus: max(x,0) + log1p(exp(-|x|))
            v = fmaxf(v, 0.0f) + log1pf(expf(-fabsf(v)));
        }
        L[r][c] = v;
    }
    __syncthreads();

    const int SIG_OFF = 0;
    const int MU_OFF  = TT * ZZ * ZZ;
    const int J_OFF   = MU_OFF + TT * ZZ;
    const int HN_OFF  = J_OFF + TT * ZZ * ZZ;

    // mu
    if (tid < ZZ) out[MU_OFF + t * ZZ + tid] = osh[tid];

    // Sigma = L L^T  (only lower entries of L referenced: k <= min(i,j))
    if (tid < ZZ * ZZ) {
        int i = tid / ZZ, jj = tid % ZZ;
        int m = (i < jj) ? i : jj;
        float sacc = 0.f;
        for (int k = 0; k <= m; k++) sacc = fmaf(L[i][k], L[jj][k], sacc);
        out[SIG_OFF + t * ZZ * ZZ + tid] = sacc;
    }

    // L^{-1}: forward substitution, one column per thread (tid = column jc)
    if (tid < ZZ) {
        const int jc = tid;
        float x[ZZ];
        #pragma unroll
        for (int i = 0; i < ZZ; i++) {
            if (i < jc) { x[i] = 0.f; continue; }
            float s2 = (i == jc) ? 1.0f : 0.0f;
            #pragma unroll
            for (int k = 0; k < ZZ; k++)
                if (k >= jc && k < i) s2 -= L[i][k] * x[k];
            x[i] = s2 / L[i][i];
            Li[i][jc] = x[i];
        }
    }
    __syncthreads();

    // J = L^{-T} L^{-1} : J[i][j] = sum_{k>=max(i,j)} Li[k][i]*Li[k][j]
    if (tid < ZZ * ZZ) {
        int i = tid / ZZ, jj = tid % ZZ;
        int m = (i > jj) ? i : jj;
        float sacc = 0.f;
        for (int k = m; k < ZZ; k++) sacc = fmaf(Li[k][i], Li[k][jj], sacc);
        Jsh[i][jj] = sacc;
        out[J_OFF + t * ZZ * ZZ + tid] = sacc;
    }
    __syncthreads();

    // h_nat = J @ mu
    if (tid < ZZ) {
        float sacc = 0.f;
        #pragma unroll
        for (int jj = 0; jj < ZZ; jj++)
            sacc = fmaf(Jsh[tid][jj], osh[jj], sacc);
        out[HN_OFF + t * ZZ + tid] = sacc;
    }
}

// ---------------------------------------------------------------------------
// Launch. Input order (metadata): carry_init, W_hr, b_hr, s_r, o_r,
// W_hz, b_hz, s_z, o_z, W_hn, b_hn, s_n, o_n, W_dense, b_dense
// ---------------------------------------------------------------------------
extern "C" void kernel_launch(void* const* d_in, const int* in_sizes, int n_in,
                              void* d_out, int out_size)
{
    const float* carry   = (const float*)d_in[0];
    const float* W_hr    = (const float*)d_in[1];
    const float* b_hr    = (const float*)d_in[2];
    const float* s_r     = (const float*)d_in[3];
    const float* o_r     = (const float*)d_in[4];
    const float* W_hz    = (const float*)d_in[5];
    const float* b_hz    = (const float*)d_in[6];
    const float* s_z     = (const float*)d_in[7];
    const float* o_z     = (const float*)d_in[8];
    const float* W_hn    = (const float*)d_in[9];
    const float* b_hn    = (const float*)d_in[10];
    const float* s_n     = (const float*)d_in[11];
    const float* o_n     = (const float*)d_in[12];
    const float* W_dense = (const float*)d_in[13];
    const float* b_dense = (const float*)d_in[14];

    gru_recurrence_kernel<<<1, 192>>>(carry,
        W_hr, b_hr, s_r, o_r,
        W_hz, b_hz, s_z, o_z,
        W_hn, b_hn, s_n, o_n);

    nat_kernel<<<TT, 128>>>(W_dense, b_dense, (float*)d_out);
}

// round 2
// speedup vs baseline: 1.6960x; 1.6960x over previous
#include <cuda_runtime.h>
#include <math.h>

#define TT  100
#define HH  50
#define ZZ  10
#define OUTD 65          // ZZ + ZZ*(ZZ+1)/2
#define NTRI 55          // ZZ*(ZZ+1)/2
#define LN_EPS 1e-6f

// scratch for hs (T x H) — __device__ global, no allocation
__device__ float g_hs[TT * HH];

__device__ __forceinline__ float fast_sigmoid(float x) {
    // 1/(1+e^-x) via MUFU EX2 + RCP. Safe at extremes (inf -> 0).
    float e = __expf(-x);
    return __fdividef(1.0f, 1.0f + e);
}

__device__ __forceinline__ float fast_tanh(float x) {
    // tanh(x) = sign(x) * (1-e)/(1+e), e = exp(-2|x|) in (0,1] -> no overflow/NaN
    float e = __expf(-2.0f * fabsf(x));
    float t = __fdividef(1.0f - e, 1.0f + e);
    return copysignf(t, x);
}

// ---------------------------------------------------------------------------
// Kernel 1: sequential GRU recurrence with layernormed gates.
// 96 threads = 3 warps, warp g owns gate g. Lane l owns columns 2l, 2l+1
// (active l < 25). Weights held entirely in registers (100 floats/lane).
// h replicated in registers per lane-pair, broadcast via SHFL.
// Exactly ONE __syncthreads per timestep (gate exchange), double-buffered.
// ---------------------------------------------------------------------------
__global__ void __launch_bounds__(96, 1) gru_recurrence_kernel(
    const float* __restrict__ carry_init,
    const float* __restrict__ W_hr, const float* __restrict__ b_hr,
    const float* __restrict__ s_r,  const float* __restrict__ o_r,
    const float* __restrict__ W_hz, const float* __restrict__ b_hz,
    const float* __restrict__ s_z,  const float* __restrict__ o_z,
    const float* __restrict__ W_hn, const float* __restrict__ b_hn,
    const float* __restrict__ s_n,  const float* __restrict__ o_n)
{
    __shared__ float gate_sh[2][3][64];   // [parity][gate][col] (padded rows)

    const int tid  = threadIdx.x;
    const int g    = tid >> 5;            // warp = gate, 0..2
    const int l    = tid & 31;            // lane
    const bool act = (l < 25);
    const int c0   = act ? 2 * l : 0;     // clamped for inactive lanes

    const float* Wg = (g == 0) ? W_hr : (g == 1) ? W_hz : W_hn;
    const float* bg = (g == 0) ? b_hr : (g == 1) ? b_hz : b_hn;
    const float* sg = (g == 0) ? s_r  : (g == 1) ? s_z  : s_n;
    const float* og = (g == 0) ? o_r  : (g == 1) ? o_z  : o_n;

    // per-lane weight columns in registers: w[i] = (W[i][c0], W[i][c0+1])
    float2 w[HH];
    #pragma unroll
    for (int i = 0; i < HH; i++)
        w[i] = *reinterpret_cast<const float2*>(Wg + i * HH + c0);

    const float b0 = bg[c0], b1 = bg[c0 + 1];
    const float sc0 = sg[c0], sc1 = sg[c0 + 1];
    const float of0 = og[c0], of1 = og[c0 + 1];

    // h state in registers (lane l holds h[2l], h[2l+1])
    float h0 = carry_init[c0];
    float h1 = carry_init[c0 + 1];

    for (int t = 0; t < TT; t++) {
        // ---- matvec: acc = b + sum_i h[i] * W[i][c0..c0+1]
        float2 a[4];
        a[0] = make_float2(b0, b1);
        a[1] = make_float2(0.f, 0.f);
        a[2] = make_float2(0.f, 0.f);
        a[3] = make_float2(0.f, 0.f);
        #pragma unroll
        for (int i = 0; i < HH; i++) {
            float hv = __shfl_sync(0xffffffffu, (i & 1) ? h1 : h0, i >> 1);
            a[i & 3].x = fmaf(hv, w[i].x, a[i & 3].x);
            a[i & 3].y = fmaf(hv, w[i].y, a[i & 3].y);
        }
        float px = (a[0].x + a[1].x) + (a[2].x + a[3].x);
        float py = (a[0].y + a[1].y) + (a[2].y + a[3].y);

        // ---- in-warp layernorm stats over this gate's 50 columns
        float sv = 0.f, qv = 0.f;
        if (act) { sv = px + py; qv = px * px + py * py; }
        #pragma unroll
        for (int off = 16; off; off >>= 1) {
            sv += __shfl_xor_sync(0xffffffffu, sv, off);
            qv += __shfl_xor_sync(0xffffffffu, qv, off);
        }
        float mean = sv * (1.0f / HH);
        float var  = qv * (1.0f / HH) - mean * mean;
        float inv  = rsqrtf(var + LN_EPS);

        float nx = (px - mean) * inv * sc0 + of0;
        float ny = (py - mean) * inv * sc1 + of1;

        float gx, gy;
        if (g < 2) { gx = fast_sigmoid(nx); gy = fast_sigmoid(ny); }
        else       { gx = nx;               gy = ny;               }

        const int buf = t & 1;
        if (act)
            *reinterpret_cast<float2*>(&gate_sh[buf][g][c0]) = make_float2(gx, gy);
        __syncthreads();

        // ---- combine gates; every warp redundantly updates its h registers
        if (act) {
            float2 rv = *reinterpret_cast<float2*>(&gate_sh[buf][0][c0]);
            float2 zv = *reinterpret_cast<float2*>(&gate_sh[buf][1][c0]);
            float2 lv = *reinterpret_cast<float2*>(&gate_sh[buf][2][c0]);
            float n0 = fast_tanh(rv.x * lv.x);
            float n1 = fast_tanh(rv.y * lv.y);
            h0 = zv.x * (h0 - n0) + n0;     // (1-z)*n + z*h
            h1 = zv.y * (h1 - n1) + n1;
            if (g == 0)
                *reinterpret_cast<float2*>(&g_hs[t * HH + c0]) = make_float2(h0, h1);
        }
    }
}

// ---------------------------------------------------------------------------
// Kernel 2: per-timestep dense + natural-parameter epilogue.
// grid = T blocks (one per timestep), 128 threads each.
// Output layout (fp32): [Sigma T*Z*Z][mu T*Z][J T*Z*Z][h_nat T*Z]
// ---------------------------------------------------------------------------
__global__ void __launch_bounds__(128, 1) nat_kernel(
    const float* __restrict__ W_dense,
    const float* __restrict__ b_dense,
    float* __restrict__ out)
{
    const int t   = blockIdx.x;
    const int tid = threadIdx.x;

    __shared__ float hsh[HH];
    __shared__ float osh[OUTD];
    __shared__ float L   [ZZ][ZZ];
    __shared__ float rdia[ZZ];
    __shared__ float Li  [ZZ][ZZ];
    __shared__ float Jsh [ZZ][ZZ];

    if (tid < HH) hsh[tid] = g_hs[t * HH + tid];
    __syncthreads();

    // dense: out[o] = b[o] + sum_i hs[t][i] * W_dense[i][o]
    if (tid < OUTD) {
        float a = b_dense[tid];
        #pragma unroll
        for (int i = 0; i < HH; i++)
            a = fmaf(hsh[i], W_dense[i * OUTD + tid], a);
        osh[tid] = a;
    }
    __syncthreads();

    // build lower-triangular L from flat part; softplus on diagonal
    if (tid < NTRI) {
        int k = tid;
        int r = (int)((sqrtf(8.0f * k + 1.0f) - 1.0f) * 0.5f);  // exact at tri bounds
        int c = k - r * (r + 1) / 2;
        float v = osh[ZZ + k];
        if (c == r) {
            // stable softplus: max(x,0) + log1p(exp(-|x|))
            v = fmaxf(v, 0.0f) + log1pf(__expf(-fabsf(v)));
            rdia[r] = __fdividef(1.0f, v);
        }
        L[r][c] = v;
    }
    __syncthreads();

    const int SIG_OFF = 0;
    const int MU_OFF  = TT * ZZ * ZZ;
    const int J_OFF   = MU_OFF + TT * ZZ;
    const int HN_OFF  = J_OFF + TT * ZZ * ZZ;

    // mu
    if (tid < ZZ) out[MU_OFF + t * ZZ + tid] = osh[tid];

    // Sigma = L L^T  (only lower entries of L referenced: k <= min(i,j))
    if (tid < ZZ * ZZ) {
        int i = tid / ZZ, jj = tid % ZZ;
        int m = (i < jj) ? i : jj;
        float sacc = 0.f;
        for (int k = 0; k <= m; k++) sacc = fmaf(L[i][k], L[jj][k], sacc);
        out[SIG_OFF + t * ZZ * ZZ + tid] = sacc;
    }

    // L^{-1}: forward substitution, one column per thread (tid = column jc)
    if (tid < ZZ) {
        const int jc = tid;
        float x[ZZ];
        #pragma unroll
        for (int i = 0; i < ZZ; i++) {
            if (i < jc) { x[i] = 0.f; continue; }
            float s2 = (i == jc) ? 1.0f : 0.0f;
            #pragma unroll
            for (int k = 0; k < ZZ; k++)
                if (k >= jc && k < i) s2 -= L[i][k] * x[k];
            x[i] = s2 * rdia[i];
            Li[i][jc] = x[i];
        }
    }
    __syncthreads();

    // J = L^{-T} L^{-1} : J[i][j] = sum_{k>=max(i,j)} Li[k][i]*Li[k][j]
    if (tid < ZZ * ZZ) {
        int i = tid / ZZ, jj = tid % ZZ;
        int m = (i > jj) ? i : jj;
        float sacc = 0.f;
        for (int k = m; k < ZZ; k++) sacc = fmaf(Li[k][i], Li[k][jj], sacc);
        Jsh[i][jj] = sacc;
        out[J_OFF + t * ZZ * ZZ + tid] = sacc;
    }
    __syncthreads();

    // h_nat = J @ mu
    if (tid < ZZ) {
        float sacc = 0.f;
        #pragma unroll
        for (int jj = 0; jj < ZZ; jj++)
            sacc = fmaf(Jsh[tid][jj], osh[jj], sacc);
        out[HN_OFF + t * ZZ + tid] = sacc;
    }
}

// ---------------------------------------------------------------------------
// Launch. Input order (metadata): carry_init, W_hr, b_hr, s_r, o_r,
// W_hz, b_hz, s_z, o_z, W_hn, b_hn, s_n, o_n, W_dense, b_dense
// ---------------------------------------------------------------------------
extern "C" void kernel_launch(void* const* d_in, const int* in_sizes, int n_in,
                              void* d_out, int out_size)
{
    const float* carry   = (const float*)d_in[0];
    const float* W_hr    = (const float*)d_in[1];
    const float* b_hr    = (const float*)d_in[2];
    const float* s_r     = (const float*)d_in[3];
    const float* o_r     = (const float*)d_in[4];
    const float* W_hz    = (const float*)d_in[5];
    const float* b_hz    = (const float*)d_in[6];
    const float* s_z     = (const float*)d_in[7];
    const float* o_z     = (const float*)d_in[8];
    const float* W_hn    = (const float*)d_in[9];
    const float* b_hn    = (const float*)d_in[10];
    const float* s_n     = (const float*)d_in[11];
    const float* o_n     = (const float*)d_in[12];
    const float* W_dense = (const float*)d_in[13];
    const float* b_dense = (const float*)d_in[14];

    gru_recurrence_kernel<<<1, 96>>>(carry,
        W_hr, b_hr, s_r, o_r,
        W_hz, b_hz, s_z, o_z,
        W_hn, b_hn, s_n, o_n);

    nat_kernel<<<TT, 128>>>(W_dense, b_dense, (float*)d_out);
}